// round 10
// baseline (speedup 1.0000x reference)
#include <cuda_runtime.h>
#include <math.h>

#define M_GT  128
#define BLOCK 256
#define APT   2            // anchors per thread

// Per-GT best-anchor key: (iou_bits << 32) | (0xFFFFFFFF - anchor_idx).
// IoU >= 0 so the float bit pattern is order-preserving under unsigned max;
// (~idx) makes the smaller anchor index win ties (matches jnp.argmax axis=0).
__device__ unsigned long long g_gt_key[M_GT];

__global__ void init_keys_kernel() {
    if (threadIdx.x < M_GT) g_gt_key[threadIdx.x] = 0ULL;
}

__device__ __forceinline__ unsigned long long pack_key(float iou, unsigned idx) {
    return (((unsigned long long)__float_as_uint(iou)) << 32) |
           (unsigned long long)(0xFFFFFFFFu - idx);
}

__device__ __forceinline__ float iou_of(float4 a, float area_a, float4 g, float sa) {
    float lx = fmaxf(a.x, g.x);
    float ly = fmaxf(a.y, g.y);
    float rx = fminf(a.z, g.z);
    float ry = fminf(a.w, g.w);
    float w  = fmaxf(rx - lx, 0.0f);
    float h  = fmaxf(ry - ly, 0.0f);
    float inter = w * h;
    return inter / (area_a + sa - inter);   // IEEE div: bit-matches reference
}

__device__ __forceinline__ void encode_write(float* __restrict__ out, int N,
                                             float4 a, float4 g, int i,
                                             bool pos, bool aligned4) {
    const float EPS = 1.1920929e-07f;  // jnp.finfo(float32).eps
    float ax = (a.x + a.z) * 0.5f;
    float ay = (a.y + a.w) * 0.5f;
    float aw = fmaxf(a.z - a.x, EPS);
    float ah = fmaxf(a.w - a.y, EPS);
    float gx = (g.x + g.z) * 0.5f;
    float gy = (g.y + g.w) * 0.5f;
    float dx = (gx - ax) / aw;
    float dy = (gy - ay) / ah;
    float dw = logf((g.z - g.x) / aw);
    float dh = logf((g.w - g.y) / ah);
    if (!pos) { dx = 0.0f; dy = 0.0f; dw = 0.0f; dh = 0.0f; }
    if (aligned4) {
        ((float4*)(out + N))[i] = make_float4(dx, dy, dw, dh);
    } else {
        float* r = out + N + 4 * i;
        r[0] = dx; r[1] = dy; r[2] = dw; r[3] = dh;
    }
}

__global__ void __launch_bounds__(BLOCK)
match_kernel(const float4* __restrict__ anchors,
             const float4* __restrict__ gts,
             const int* __restrict__ labels,
             float* __restrict__ out,
             int N, int M, int aligned4)
{
    __shared__ float4 sgt[M_GT];
    __shared__ float  sarea[M_GT];
    __shared__ int    slab[M_GT];
    __shared__ unsigned long long skey[M_GT];

    int tid = threadIdx.x;
    for (int j = tid; j < M_GT; j += BLOCK) {
        if (j < M) {
            float4 g = gts[j];
            sgt[j]   = g;
            sarea[j] = (g.z - g.x) * (g.w - g.y);
            slab[j]  = labels[j];
        }
        skey[j] = 0ULL;
    }
    __syncthreads();

    int  base = blockIdx.x * (BLOCK * APT);
    int  i0 = base + tid;
    int  i1 = i0 + BLOCK;
    bool act0 = (i0 < N);
    bool act1 = (i1 < N);
    float4 a0 = anchors[act0 ? i0 : 0];
    float4 a1 = anchors[act1 ? i1 : 0];
    float area0 = (a0.z - a0.x) * (a0.w - a0.y);
    float area1 = (a1.z - a1.x) * (a1.w - a1.y);

    float best0 = -1.0f, best1 = -1.0f;
    int   bj0 = 0, bj1 = 0;

    volatile unsigned* skey_hi = (volatile unsigned*)skey;  // [2*j+1] = iou bits

    #pragma unroll 4
    for (int j = 0; j < M; ++j) {
        float4 g  = sgt[j];
        float  sa = sarea[j];

        float iou0 = iou_of(a0, area0, g, sa);
        float iou1 = iou_of(a1, area1, g, sa);
        if (!act0) iou0 = -1.0f;
        if (!act1) iou1 = -1.0f;

        // per-anchor argmax over GTs (strict '>' keeps first j = jnp tie-break)
        if (iou0 > best0) { best0 = iou0; bj0 = j; }
        if (iou1 > best1) { best1 = iou1; bj1 = j; }

        // per-GT argmax: racy pre-check against the block's visible best,
        // atomicMax is the authority. Stale 'hi' only causes extra atomics.
        float hi = __uint_as_float(skey_hi[2 * j + 1]);
        float mx = fmaxf(iou0, iou1);
        if (mx > 0.0f && mx >= hi) {
            unsigned long long k0 = (iou0 > 0.0f) ? pack_key(iou0, (unsigned)i0) : 0ULL;
            unsigned long long k1 = (iou1 > 0.0f) ? pack_key(iou1, (unsigned)i1) : 0ULL;
            atomicMax(&skey[j], k0 > k1 ? k0 : k1);
        }
    }
    __syncthreads();
    if (tid < M)
        atomicMax(&g_gt_key[tid], skey[tid]);   // one L2 atomic per (block, GT)

    bool al4 = (aligned4 != 0);
    if (act0) {
        bool pos = (best0 >= 0.5f);
        bool neg = (best0 < 0.4f) && !pos;
        out[i0] = (float)(pos ? slab[bj0] : (neg ? 0 : -1));
        encode_write(out, N, a0, sgt[bj0], i0, pos, al4);
        out[5 * N + i0] = pos ? 1.0f : 0.0f;
    }
    if (act1) {
        bool pos = (best1 >= 0.5f);
        bool neg = (best1 < 0.4f) && !pos;
        out[i1] = (float)(pos ? slab[bj1] : (neg ? 0 : -1));
        encode_write(out, N, a1, sgt[bj1], i1, pos, al4);
        out[5 * N + i1] = pos ? 1.0f : 0.0f;
    }
}

// Force best-anchor-per-GT positive. Recomputes that anchor's per-anchor
// argmax; duplicate concurrent writes are identical, so deterministic.
__global__ void fix_kernel(const float4* __restrict__ anchors,
                           const float4* __restrict__ gts,
                           const int* __restrict__ labels,
                           float* __restrict__ out,
                           int N, int M, int aligned4)
{
    __shared__ float4 sgt[M_GT];
    __shared__ float  sarea[M_GT];
    int t = threadIdx.x;
    if (t < M) {
        float4 g = gts[t];
        sgt[t]   = g;
        sarea[t] = (g.z - g.x) * (g.w - g.y);
    }
    __syncthreads();
    if (t >= M) return;

    unsigned long long key = g_gt_key[t];
    // key==0 => no anchor had iou>0 for this GT; jnp.argmax of all-zero col = 0
    int idx = (key == 0ULL) ? 0
            : (int)(0xFFFFFFFFu - (unsigned)(key & 0xFFFFFFFFULL));
    if (idx < 0 || idx >= N) return;

    float4 a = anchors[idx];
    float area_a = (a.z - a.x) * (a.w - a.y);
    float best = -1.0f;
    int   bestj = 0;
    for (int j = 0; j < M; ++j) {
        float iou = iou_of(a, area_a, sgt[j], sarea[j]);
        if (iou > best) { best = iou; bestj = j; }
    }

    out[idx] = (float)labels[bestj];
    encode_write(out, N, a, sgt[bestj], idx, true, aligned4 != 0);
    out[5 * N + idx] = 1.0f;
}

extern "C" void kernel_launch(void* const* d_in, const int* in_sizes, int n_in,
                              void* d_out, int out_size)
{
    const float4* anchors = (const float4*)d_in[0];
    const float4* gts     = (const float4*)d_in[1];
    const int*    labels  = (const int*)d_in[2];
    float*        out     = (float*)d_out;

    int N = in_sizes[0] / 4;
    int M = in_sizes[2];
    if (M > M_GT) M = M_GT;
    int aligned4 = ((N & 3) == 0) ? 1 : 0;

    init_keys_kernel<<<1, 128>>>();
    int blocks = (N + BLOCK * APT - 1) / (BLOCK * APT);
    match_kernel<<<blocks, BLOCK>>>(anchors, gts, labels, out, N, M, aligned4);
    fix_kernel<<<1, 128>>>(anchors, gts, labels, out, N, M, aligned4);
}

// round 11
// speedup vs baseline: 1.0514x; 1.0514x over previous
#include <cuda_runtime.h>
#include <math.h>

#define M_GT  128
#define BLOCK 128
#define APT   4            // anchors per thread

// Per-GT best-anchor key: (iou_bits << 32) | (0xFFFFFFFF - anchor_idx).
// IoU >= 0 so float bits are order-preserving under unsigned max; ~idx makes
// the smaller anchor index win ties (matches jnp.argmax axis=0 tie-break).
__device__ unsigned long long g_gt_key[M_GT];

__global__ void init_keys_kernel() {
    if (threadIdx.x < M_GT) g_gt_key[threadIdx.x] = 0ULL;
}

__device__ __forceinline__ unsigned long long pack_key(float iou, unsigned idx) {
    return (((unsigned long long)__float_as_uint(iou)) << 32) |
           (unsigned long long)(0xFFFFFFFFu - idx);
}

__device__ __forceinline__ void encode_write(float* __restrict__ out, int N,
                                             float4 a, float4 g, int i,
                                             bool pos, bool aligned4) {
    const float EPS = 1.1920929e-07f;  // jnp.finfo(float32).eps
    float ax = (a.x + a.z) * 0.5f;
    float ay = (a.y + a.w) * 0.5f;
    float aw = fmaxf(a.z - a.x, EPS);
    float ah = fmaxf(a.w - a.y, EPS);
    float gx = (g.x + g.z) * 0.5f;
    float gy = (g.y + g.w) * 0.5f;
    float dx = (gx - ax) / aw;
    float dy = (gy - ay) / ah;
    float dw = logf((g.z - g.x) / aw);
    float dh = logf((g.w - g.y) / ah);
    if (!pos) { dx = 0.0f; dy = 0.0f; dw = 0.0f; dh = 0.0f; }
    if (aligned4) {
        ((float4*)(out + N))[i] = make_float4(dx, dy, dw, dh);
    } else {
        float* r = out + N + 4 * i;
        r[0] = dx; r[1] = dy; r[2] = dw; r[3] = dh;
    }
}

__global__ void __launch_bounds__(BLOCK)
match_kernel(const float4* __restrict__ anchors,
             const float4* __restrict__ gts,
             const int* __restrict__ labels,
             float* __restrict__ out,
             int N, int M, int aligned4)
{
    __shared__ float4 sgt[M_GT];
    __shared__ float  sarea[M_GT];
    __shared__ int    slab[M_GT];
    __shared__ unsigned long long skey[M_GT];

    int tid = threadIdx.x;
    for (int j = tid; j < M_GT; j += BLOCK) {
        if (j < M) {
            float4 g = gts[j];
            sgt[j]   = g;
            sarea[j] = (g.z - g.x) * (g.w - g.y);
            slab[j]  = labels[j];
        }
        skey[j] = 0ULL;
    }
    __syncthreads();

    int base = blockIdx.x * (BLOCK * APT);

    int    idx[APT];
    bool   act[APT];
    float4 a[APT];
    float  area[APT];
    // per-anchor argmax state: best (inter, den) pair + index; division-free.
    float  binter[APT], bden[APT];
    int    bj[APT];

    #pragma unroll
    for (int k = 0; k < APT; ++k) {
        idx[k] = base + k * BLOCK + tid;
        act[k] = (idx[k] < N);
        a[k]   = anchors[act[k] ? idx[k] : 0];
        area[k] = (a[k].z - a[k].x) * (a[k].w - a[k].y);
        binter[k] = -1.0f;   // j=0 always wins the first compare (den > 0)
        bden[k]   = 1.0f;
        bj[k]     = 0;
    }

    const unsigned* skey_hi = (const unsigned*)skey;  // [2*j+1] = iou bits (LE)

    for (int j = 0; j < M; ++j) {
        float4 g  = sgt[j];
        float  sa = sarea[j];
        // racy read of block-best iou for GT j; staleness only adds atomics
        float hi = __uint_as_float(skey_hi[2 * j + 1]);
        float hc = hi * 0.99999f;   // conservative margin: never filter winner

        unsigned long long bestk = 0ULL;

        #pragma unroll
        for (int k = 0; k < APT; ++k) {
            float lx = fmaxf(a[k].x, g.x);
            float ly = fmaxf(a[k].y, g.y);
            float rx = fminf(a[k].z, g.z);
            float ry = fminf(a[k].w, g.w);
            float w  = fmaxf(rx - lx, 0.0f);
            float h  = fmaxf(ry - ly, 0.0f);
            float inter    = w * h;
            float area_sum = area[k] + sa;        // reference eval order
            float den      = area_sum - inter;    // > 0 always

            // per-anchor argmax, division-free: iou_j > iou_best
            //   <=> inter_j * den_best > inter_best * den_j   (dens > 0)
            // strict '>' keeps first j (jnp tie-break on rounded values ~)
            if (act[k] && inter * bden[k] > binter[k] * den) {
                binter[k] = inter; bden[k] = den; bj[k] = j;
            }

            // per-GT pre-check, division-free:
            //   iou >= hc  <=>  inter*(1+hc) >= hc*area_sum
            if (act[k] && inter > 0.0f &&
                fmaf(hc, inter, inter) >= hc * area_sum) {
                float iou = __fdiv_rn(inter, den);   // exact, reference-rounded
                unsigned long long kk = pack_key(iou, (unsigned)idx[k]);
                if (kk > bestk) bestk = kk;
            }
        }

        if (bestk) {
            // double-check against freshest value to damp atomic storms
            if (bestk > *((volatile unsigned long long*)&skey[j]))
                atomicMax(&skey[j], bestk);
        }
    }
    __syncthreads();
    if (tid < M)
        atomicMax(&g_gt_key[tid], skey[tid]);   // one L2 atomic per (block, GT)

    bool al4 = (aligned4 != 0);
    #pragma unroll
    for (int k = 0; k < APT; ++k) {
        if (!act[k]) continue;
        float best = __fdiv_rn(binter[k], bden[k]);  // reference-rounded max IoU
        bool pos = (best >= 0.5f);
        bool neg = (best < 0.4f) && !pos;
        out[idx[k]] = (float)(pos ? slab[bj[k]] : (neg ? 0 : -1));
        encode_write(out, N, a[k], sgt[bj[k]], idx[k], pos, al4);
        out[5 * N + idx[k]] = pos ? 1.0f : 0.0f;
    }
}

// Force best-anchor-per-GT positive. Recomputes that anchor's per-anchor
// argmax with exact IEEE division; duplicate concurrent writes (several GTs
// sharing one best anchor) produce identical values => deterministic.
__global__ void fix_kernel(const float4* __restrict__ anchors,
                           const float4* __restrict__ gts,
                           const int* __restrict__ labels,
                           float* __restrict__ out,
                           int N, int M, int aligned4)
{
    __shared__ float4 sgt[M_GT];
    __shared__ float  sarea[M_GT];
    int t = threadIdx.x;
    if (t < M) {
        float4 g = gts[t];
        sgt[t]   = g;
        sarea[t] = (g.z - g.x) * (g.w - g.y);
    }
    __syncthreads();
    if (t >= M) return;

    unsigned long long key = g_gt_key[t];
    // key==0 => all ious for this GT were 0; jnp.argmax of all-zero col = 0
    int idx = (key == 0ULL) ? 0
            : (int)(0xFFFFFFFFu - (unsigned)(key & 0xFFFFFFFFULL));
    if (idx < 0 || idx >= N) return;

    float4 a = anchors[idx];
    float area_a = (a.z - a.x) * (a.w - a.y);
    float best = -1.0f;
    int   bestj = 0;
    for (int j = 0; j < M; ++j) {
        float4 g = sgt[j];
        float lx = fmaxf(a.x, g.x);
        float ly = fmaxf(a.y, g.y);
        float rx = fminf(a.z, g.z);
        float ry = fminf(a.w, g.w);
        float w  = fmaxf(rx - lx, 0.0f);
        float h  = fmaxf(ry - ly, 0.0f);
        float inter = w * h;
        float iou = __fdiv_rn(inter, (area_a + sarea[j]) - inter);
        if (iou > best) { best = iou; bestj = j; }   // first-max tie-break
    }

    out[idx] = (float)labels[bestj];
    encode_write(out, N, a, sgt[bestj], idx, true, aligned4 != 0);
    out[5 * N + idx] = 1.0f;
}

extern "C" void kernel_launch(void* const* d_in, const int* in_sizes, int n_in,
                              void* d_out, int out_size)
{
    const float4* anchors = (const float4*)d_in[0];
    const float4* gts     = (const float4*)d_in[1];
    const int*    labels  = (const int*)d_in[2];
    float*        out     = (float*)d_out;

    int N = in_sizes[0] / 4;
    int M = in_sizes[2];
    if (M > M_GT) M = M_GT;
    int aligned4 = ((N & 3) == 0) ? 1 : 0;

    init_keys_kernel<<<1, 128>>>();
    int blocks = (N + BLOCK * APT - 1) / (BLOCK * APT);
    match_kernel<<<blocks, BLOCK>>>(anchors, gts, labels, out, N, M, aligned4);
    fix_kernel<<<1, 128>>>(anchors, gts, labels, out, N, M, aligned4);
}

// round 12
// speedup vs baseline: 1.3235x; 1.2588x over previous
#include <cuda_runtime.h>
#include <math.h>

#define M_GT  128
#define BLOCK 128
#define APT   4            // anchors per thread

// Per-GT best-anchor key: (iou_bits << 32) | (0xFFFFFFFF - anchor_idx).
// IoU >= 0 so float bits are order-preserving under unsigned max; ~idx makes
// the smaller anchor index win ties (matches jnp.argmax axis=0 tie-break).
// Zero-initialized at module load; fix_kernel re-zeros it after each use, so
// every kernel_launch invocation (and every graph replay) starts from 0.
__device__ unsigned long long g_gt_key[M_GT];

__device__ __forceinline__ unsigned long long pack_key(float iou, unsigned idx) {
    return (((unsigned long long)__float_as_uint(iou)) << 32) |
           (unsigned long long)(0xFFFFFFFFu - idx);
}

__device__ __forceinline__ void encode_write(float* __restrict__ out, int N,
                                             float4 a, float4 g, int i,
                                             bool pos, bool aligned4) {
    const float EPS = 1.1920929e-07f;  // jnp.finfo(float32).eps
    float ax = (a.x + a.z) * 0.5f;
    float ay = (a.y + a.w) * 0.5f;
    float aw = fmaxf(a.z - a.x, EPS);
    float ah = fmaxf(a.w - a.y, EPS);
    float gx = (g.x + g.z) * 0.5f;
    float gy = (g.y + g.w) * 0.5f;
    float dx = (gx - ax) / aw;
    float dy = (gy - ay) / ah;
    float dw = logf((g.z - g.x) / aw);
    float dh = logf((g.w - g.y) / ah);
    if (!pos) { dx = 0.0f; dy = 0.0f; dw = 0.0f; dh = 0.0f; }
    if (aligned4) {
        ((float4*)(out + N))[i] = make_float4(dx, dy, dw, dh);
    } else {
        float* r = out + N + 4 * i;
        r[0] = dx; r[1] = dy; r[2] = dw; r[3] = dh;
    }
}

__global__ void __launch_bounds__(BLOCK)
match_kernel(const float4* __restrict__ anchors,
             const float4* __restrict__ gts,
             const int* __restrict__ labels,
             float* __restrict__ out,
             int N, int M, int aligned4)
{
    __shared__ float4 sgt[M_GT];
    __shared__ float  sarea[M_GT];
    __shared__ int    slab[M_GT];
    __shared__ unsigned long long skey[M_GT];

    int tid  = threadIdx.x;
    int lane = tid & 31;
    for (int j = tid; j < M_GT; j += BLOCK) {
        if (j < M) {
            float4 g = gts[j];
            sgt[j]   = g;
            sarea[j] = (g.z - g.x) * (g.w - g.y);
            slab[j]  = labels[j];
        }
        skey[j] = 0ULL;
    }
    __syncthreads();

    int base = blockIdx.x * (BLOCK * APT);

    unsigned idx[APT];
    bool     act[APT];
    float4   a[APT];
    float    area[APT];
    // per-anchor argmax state (axis=1), division-free: best (inter, den) + j
    float    binter[APT], bden[APT];
    int      bj[APT];

    #pragma unroll
    for (int k = 0; k < APT; ++k) {
        idx[k]  = (unsigned)(base + k * BLOCK + tid);
        act[k]  = (idx[k] < (unsigned)N);
        a[k]    = anchors[act[k] ? idx[k] : 0];
        area[k] = (a[k].z - a[k].x) * (a[k].w - a[k].y);
        binter[k] = -1.0f;   // j=0 always wins the first compare (den > 0)
        bden[k]   = 1.0f;
        bj[k]     = 0;
    }

    const unsigned* skey_hi = (const unsigned*)skey;  // [2*j+1] = iou bits (LE)

    for (int j = 0; j < M; ++j) {
        float4 g  = sgt[j];
        float  sa = sarea[j];

        // lane's tournament candidate for GT j: best over its APT anchors
        float    ti = 0.0f, td = 1.0f;
        unsigned tx = 0xFFFFFFFFu;

        #pragma unroll
        for (int k = 0; k < APT; ++k) {
            float lx = fmaxf(a[k].x, g.x);
            float ly = fmaxf(a[k].y, g.y);
            float rx = fminf(a[k].z, g.z);
            float ry = fminf(a[k].w, g.w);
            float w  = fmaxf(rx - lx, 0.0f);
            float h  = fmaxf(ry - ly, 0.0f);
            float inter    = w * h;
            float area_sum = area[k] + sa;      // reference eval order
            float den      = area_sum - inter;  // > 0 always
            if (!act[k]) inter = 0.0f;

            // per-anchor argmax (axis=1), strict '>' keeps first j
            if (inter * bden[k] > binter[k] * den) {
                binter[k] = inter; bden[k] = den; bj[k] = j;
            }
            // lane candidate (axis=0), strict '>' prefers smaller k = smaller idx
            if (inter * td > ti * den) {
                ti = inter; td = den; tx = idx[k];
            }
        }

        // warp tournament, division-free cross-mult compare; symmetric
        // products + idx tie-break => all lanes converge to one winner.
        #pragma unroll
        for (int off = 16; off; off >>= 1) {
            float    oi = __shfl_xor_sync(0xFFFFFFFFu, ti, off);
            float    od = __shfl_xor_sync(0xFFFFFFFFu, td, off);
            unsigned ox = __shfl_xor_sync(0xFFFFFFFFu, tx, off);
            float p_o = oi * td;   // other's iou * my den scale
            float p_m = ti * od;
            bool take = (p_o > p_m) || ((p_o == p_m) && (ox < tx));
            if (take) { ti = oi; td = od; tx = ox; }
        }

        if (lane == 0 && ti > 0.0f) {
            // racy skip vs block's visible best (warms within this j across
            // warps); conservative margin; atomicMax is the authority.
            float hi = __uint_as_float(skey_hi[2 * j + 1]);
            float hc = hi * 0.999999f;
            float s  = ti + td;                    // = area_sum of winner
            if (fmaf(hc, ti, ti) >= hc * s) {
                float iou = __fdiv_rn(ti, td);     // exact, reference-rounded
                atomicMax(&skey[j], pack_key(iou, tx));
            }
        }
    }
    __syncthreads();
    if (tid < M && skey[tid] != 0ULL)
        atomicMax(&g_gt_key[tid], skey[tid]);  // <=1 L2 atomic per (block, GT)

    bool al4 = (aligned4 != 0);
    #pragma unroll
    for (int k = 0; k < APT; ++k) {
        if (!act[k]) continue;
        float best = __fdiv_rn(binter[k], bden[k]);  // reference-rounded max IoU
        bool pos = (best >= 0.5f);
        bool neg = (best < 0.4f) && !pos;
        out[idx[k]] = (float)(pos ? slab[bj[k]] : (neg ? 0 : -1));
        encode_write(out, N, a[k], sgt[bj[k]], idx[k], pos, al4);
        out[5 * N + idx[k]] = pos ? 1.0f : 0.0f;
    }
}

// Force best-anchor-per-GT positive, then reset g_gt_key for the next replay.
// Duplicate concurrent writes (several GTs sharing one best anchor) produce
// identical values => deterministic.
__global__ void fix_kernel(const float4* __restrict__ anchors,
                           const float4* __restrict__ gts,
                           const int* __restrict__ labels,
                           float* __restrict__ out,
                           int N, int M, int aligned4)
{
    __shared__ float4 sgt[M_GT];
    __shared__ float  sarea[M_GT];
    int t = threadIdx.x;
    if (t < M) {
        float4 g = gts[t];
        sgt[t]   = g;
        sarea[t] = (g.z - g.x) * (g.w - g.y);
    }
    __syncthreads();
    if (t >= M_GT) return;

    unsigned long long key = g_gt_key[t];
    g_gt_key[t] = 0ULL;                 // restore invariant for next launch
    if (t >= M) return;

    // key==0 => all ious for this GT were 0; jnp.argmax of all-zero col = 0
    int idx = (key == 0ULL) ? 0
            : (int)(0xFFFFFFFFu - (unsigned)(key & 0xFFFFFFFFULL));
    if (idx < 0 || idx >= N) return;

    float4 a = anchors[idx];
    float area_a = (a.z - a.x) * (a.w - a.y);
    float best = -1.0f;
    int   bestj = 0;
    for (int j = 0; j < M; ++j) {
        float4 g = sgt[j];
        float lx = fmaxf(a.x, g.x);
        float ly = fmaxf(a.y, g.y);
        float rx = fminf(a.z, g.z);
        float ry = fminf(a.w, g.w);
        float w  = fmaxf(rx - lx, 0.0f);
        float h  = fmaxf(ry - ly, 0.0f);
        float inter = w * h;
        float iou = __fdiv_rn(inter, (area_a + sarea[j]) - inter);
        if (iou > best) { best = iou; bestj = j; }   // first-max tie-break
    }

    out[idx] = (float)labels[bestj];
    encode_write(out, N, a, sgt[bestj], idx, true, aligned4 != 0);
    out[5 * N + idx] = 1.0f;
}

extern "C" void kernel_launch(void* const* d_in, const int* in_sizes, int n_in,
                              void* d_out, int out_size)
{
    const float4* anchors = (const float4*)d_in[0];
    const float4* gts     = (const float4*)d_in[1];
    const int*    labels  = (const int*)d_in[2];
    float*        out     = (float*)d_out;

    int N = in_sizes[0] / 4;
    int M = in_sizes[2];
    if (M > M_GT) M = M_GT;
    int aligned4 = ((N & 3) == 0) ? 1 : 0;

    int blocks = (N + BLOCK * APT - 1) / (BLOCK * APT);
    match_kernel<<<blocks, BLOCK>>>(anchors, gts, labels, out, N, M, aligned4);
    fix_kernel<<<1, 128>>>(anchors, gts, labels, out, N, M, aligned4);
}